// round 16
// baseline (speedup 1.0000x reference)
#include <cuda_runtime.h>
#include <cuda_fp16.h>
#include <math.h>
#include <stdint.h>

// ---------------- problem constants ----------------
#define Bc   4
#define Lc   2048
#define Dc   1024
#define Hc   4
#define HDc  256
#define NLc  2
#define FFc  4096
#define Mc   (Bc*Lc)     // 8192 tokens
#define D3c  (3*Dc)      // 3072

// ---------------- device scratch (static; no allocations) ----------------
__device__ __align__(16) __half g_h  [(size_t)Mc*Dc];        // residual fp16
__device__ __align__(16) __half g_x  [(size_t)Mc*D3c];
__device__ __align__(16) __half g_w3 [(size_t)Dc*D3c];
__device__ __align__(16) __half g_wq [(size_t)NLc*D3c*Dc];
__device__ __align__(16) __half g_wp [(size_t)NLc*Dc*Dc];
__device__ __align__(16) __half g_w1 [(size_t)NLc*FFc*Dc];
__device__ __align__(16) __half g_w2 [(size_t)NLc*Dc*FFc];
__device__ __align__(16) __half g_qv [(size_t)Mc*D3c];
__device__ __align__(16) __half g_vt [(size_t)Bc*Hc*HDc*Lc];
__device__ __align__(16) __half g_p  [(size_t)Bc*Hc*Lc*Lc]; // exp(logits), unnormalized
__device__ __align__(8)  float  g_sm [(size_t)Bc*Hc*Lc];    // per-row sum of exps
__device__ __align__(8)  float2 g_st4[(size_t)Mc*4];        // per-row (sum,sumsq) partials x4
__device__ __align__(16) __half g_o  [(size_t)Mc*Dc];
__device__ __align__(16) __half g_f  [(size_t)Mc*FFc];

// ---------------- helpers ----------------
__device__ __forceinline__ uint32_t smem_u32(const void* p) {
    uint32_t a;
    asm("{ .reg .u64 t; cvta.to.shared.u64 t, %1; cvt.u32.u64 %0, t; }" : "=r"(a) : "l"(p));
    return a;
}
__device__ __forceinline__ void ldsm4(uint32_t* r, uint32_t addr) {
    asm volatile("ldmatrix.sync.aligned.m8n8.x4.shared.b16 {%0,%1,%2,%3}, [%4];"
        : "=r"(r[0]), "=r"(r[1]), "=r"(r[2]), "=r"(r[3]) : "r"(addr));
}
__device__ __forceinline__ void mma_hf(float* d, const uint32_t* a, const uint32_t* b) {
    asm volatile(
        "mma.sync.aligned.m16n8k16.row.col.f32.f16.f16.f32 "
        "{%0,%1,%2,%3}, {%4,%5,%6,%7}, {%8,%9}, {%0,%1,%2,%3};"
        : "+f"(d[0]), "+f"(d[1]), "+f"(d[2]), "+f"(d[3])
        : "r"(a[0]), "r"(a[1]), "r"(a[2]), "r"(a[3]), "r"(b[0]), "r"(b[1]));
}
__device__ __forceinline__ void cpa16(uint32_t dst, const void* src) {
    asm volatile("cp.async.cg.shared.global [%0], [%1], 16;" :: "r"(dst), "l"(src));
}
#define CP_COMMIT() asm volatile("cp.async.commit_group;" ::: "memory")
#define CP_WAIT1()  asm volatile("cp.async.wait_group 1;"  ::: "memory")

__device__ __forceinline__ float gelu_exact(float x) {
    return 0.5f * x * (1.0f + erff(x * 0.70710678118654752440f));
}
__device__ __forceinline__ uint2 conv4h(float4 v) {
    union { __half2 h2[2]; uint2 u; } H;
    H.h2[0] = __halves2half2(__float2half_rn(v.x), __float2half_rn(v.y));
    H.h2[1] = __halves2half2(__float2half_rn(v.z), __float2half_rn(v.w));
    return H.u;
}
__device__ __forceinline__ float4 h4_to_f4(uint2 u) {
    union { uint2 uu; __half2 h2[2]; } U; U.uu = u;
    float2 lo = __half22float2(U.h2[0]);
    float2 hi = __half22float2(U.h2[1]);
    return make_float4(lo.x, lo.y, hi.x, hi.y);
}
// layernorm-apply on 8 packed halves: (v-m)*rs*g[k]+b[k]
__device__ __forceinline__ uint4 ln8h(uint4 raw, float m, float rs,
                                      const float* g, const float* b, int kk) {
    float4 f0 = h4_to_f4(make_uint2(raw.x, raw.y));
    float4 f1 = h4_to_f4(make_uint2(raw.z, raw.w));
    float4 g0 = *(const float4*)&g[kk];
    float4 g1 = *(const float4*)&g[kk + 4];
    float4 b0 = *(const float4*)&b[kk];
    float4 b1 = *(const float4*)&b[kk + 4];
    f0.x = (f0.x - m) * rs * g0.x + b0.x;
    f0.y = (f0.y - m) * rs * g0.y + b0.y;
    f0.z = (f0.z - m) * rs * g0.z + b0.z;
    f0.w = (f0.w - m) * rs * g0.w + b0.w;
    f1.x = (f1.x - m) * rs * g1.x + b1.x;
    f1.y = (f1.y - m) * rs * g1.y + b1.y;
    f1.z = (f1.z - m) * rs * g1.z + b1.z;
    f1.w = (f1.w - m) * rs * g1.w + b1.w;
    uint2 e0 = conv4h(f0), e1 = conv4h(f1);
    return make_uint4(e0.x, e0.y, e1.x, e1.y);
}

// ================= fp16 1-term GEMM, CTA tile 128x256, fp16 out =================
// MODE 0: C = act(scale*A@B^T + bias + resid)
// MODE 1: C = exp(scale*A@B^T), atomicAdd per-row sums into rowsum
// MODE 2: C = (A@B^T) * (1/rowsum[row])
// STATS : epilogue writes per-row (sum,sumsq) partial to st4[row*4+blockIdx.x]
// LNA   : A-loader applies layernorm using st4 + lng/lnb
#define KC     64
#define SKB    72
#define A_TILE (128*SKB*2)          // 18432 B
#define B_TILE (256*SKB*2)          // 36864 B
#define STG    (A_TILE + B_TILE)    // 55296 B
#define SM1    (3*STG)              // 165888 B dynamic smem

template<bool HB, bool HR, int ACT, int MODE, bool STATS, bool LNA>
__global__ __launch_bounds__(256, 1) void tc_ghf(
    const __half* __restrict__ Ah, int lda,
    const __half* __restrict__ Bh, int ldb,
    const float* __restrict__ bias,
    const __half* __restrict__ resid,
    float* __restrict__ rowsum, long sto, long sti,
    float2* __restrict__ st4,
    const float* __restrict__ lng, const float* __restrict__ lnb,
    __half* __restrict__ Cho, int ldc,
    int K, float scale,
    long aso, long asi, long bso, long bsi, long cso, long csi, int zinner)
{
    const int z  = blockIdx.z;
    const int zo = z / zinner;
    const int zi = z - zo * zinner;
    const size_t aofs = (size_t)zo * aso + (size_t)zi * asi;
    const size_t bofs = (size_t)zo * bso + (size_t)zi * bsi;
    const size_t cofs = (size_t)zo * cso + (size_t)zi * csi;
    Ah += aofs;
    Bh += bofs;

    extern __shared__ char dsm[];
    const uint32_t sb32 = smem_u32(dsm);

    const int tid  = threadIdx.x;
    const int wid  = tid >> 5;
    const int lane = tid & 31;
    const int wr   = wid & 3;
    const int wc   = wid >> 2;
    const int row0 = blockIdx.y * 128;
    const int col0 = blockIdx.x * 256;

    const int lr0 = tid >> 3;
    const int lc8 = (tid & 7) << 3;

    const __half* A0 = Ah + (size_t)row0 * lda;
    const __half* B0 = Bh + (size_t)col0 * ldb;

    float* RS = (MODE != 0) ? rowsum + (size_t)zo * sto + (size_t)zi * sti : nullptr;

    // LNA: per-loader-row mean/rstd from 4 stat partials
    float lnm[4], lnr[4];
    if (LNA) {
        #pragma unroll
        for (int it = 0; it < 4; it++) {
            int r = row0 + lr0 + it * 32;
            float2 p0 = st4[4*r], p1 = st4[4*r+1], p2 = st4[4*r+2], p3 = st4[4*r+3];
            float s1 = p0.x + p1.x + p2.x + p3.x;
            float s2 = p0.y + p1.y + p2.y + p3.y;
            float m  = s1 * (1.0f / Dc);
            float va = s2 * (1.0f / Dc) - m * m;
            lnm[it] = m;
            lnr[it] = rsqrtf(va + 1e-5f);
        }
    }

    float acc[2][16][4];
    #pragma unroll
    for (int mt = 0; mt < 2; mt++)
        #pragma unroll
        for (int nt = 0; nt < 16; nt++)
            #pragma unroll
            for (int j = 0; j < 4; j++) acc[mt][nt][j] = 0.0f;

    const int nc = K / KC;

    auto loadA = [&](int stg, int k0) {
        uint32_t base = sb32 + (uint32_t)stg * STG;
        #pragma unroll
        for (int it = 0; it < 4; it++) {
            int r = lr0 + it * 32;
            cpa16(base + (uint32_t)(r * SKB + lc8) * 2, A0 + (size_t)r * lda + k0 + lc8);
        }
    };
    auto loadAln = [&](int stg, int k0) {
        #pragma unroll
        for (int it = 0; it < 4; it++) {
            int r = lr0 + it * 32;
            uint4 raw = *(const uint4*)(A0 + (size_t)r * lda + k0 + lc8);
            *(uint4*)(dsm + (size_t)stg * STG + (size_t)(r * SKB + lc8) * 2) =
                ln8h(raw, lnm[it], lnr[it], lng, lnb, k0 + lc8);
        }
    };
    auto loadB = [&](int stg, int k0) {
        uint32_t base = sb32 + (uint32_t)stg * STG;
        #pragma unroll
        for (int it = 0; it < 8; it++) {
            int r = lr0 + it * 32;
            cpa16(base + A_TILE + (uint32_t)(r * SKB + lc8) * 2, B0 + (size_t)r * ldb + k0 + lc8);
        }
    };

    // prologue
    if (LNA) { loadAln(0, 0); if (nc > 1) loadAln(1, KC); }
    else     { loadA(0, 0);   if (nc > 1) loadA(1, KC); }
    loadB(0, 0);
    CP_COMMIT();
    if (nc > 1) loadB(1, KC);
    CP_COMMIT();

    const int ro = lane & 15;
    const int co = (lane >> 4) << 3;

    for (int c = 0; c < nc; c++) {
        CP_WAIT1();
        __syncthreads();

        const bool pf2 = (c + 2 < nc);
        const int k2 = (c + 2) * KC;
        const int s2g = (c + 2) % 3;

        uint4 ra[4];
        if (LNA && pf2) {
            #pragma unroll
            for (int it = 0; it < 4; it++) {
                int r = lr0 + it * 32;
                ra[it] = *(const uint4*)(A0 + (size_t)r * lda + k2 + lc8);
            }
        }
        if (pf2) {
            if (!LNA) loadA(s2g, k2);
            loadB(s2g, k2);
        }
        CP_COMMIT();

        const uint32_t sOff = sb32 + (uint32_t)(c % 3) * STG;
        #pragma unroll
        for (int ks = 0; ks < 4; ks++) {
            const int k0 = ks * 16;
            uint32_t ah[2][4];
            #pragma unroll
            for (int mt = 0; mt < 2; mt++) {
                uint32_t off = (uint32_t)((32*wr + 16*mt + ro) * SKB + k0 + co) * 2;
                ldsm4(ah[mt], sOff + off);
            }
            uint32_t bh[16][2];
            #pragma unroll
            for (int p = 0; p < 8; p++) {
                uint32_t off = (uint32_t)((128*wc + 16*p + ro) * SKB + k0 + co) * 2;
                uint32_t r[4];
                ldsm4(r, sOff + A_TILE + off);
                bh[2*p][0] = r[0];   bh[2*p][1] = r[2];
                bh[2*p+1][0] = r[1]; bh[2*p+1][1] = r[3];
            }
            #pragma unroll
            for (int mt = 0; mt < 2; mt++)
                #pragma unroll
                for (int nt = 0; nt < 16; nt++)
                    mma_hf(acc[mt][nt], ah[mt], bh[nt]);
        }

        if (LNA && pf2) {
            #pragma unroll
            for (int it = 0; it < 4; it++) {
                int r = lr0 + it * 32;
                *(uint4*)(dsm + (size_t)s2g * STG + (size_t)(r * SKB + lc8) * 2) =
                    ln8h(ra[it], lnm[it], lnr[it], lng, lnb, k2 + lc8);
            }
        }
        __syncthreads();
    }

    // ---- epilogue ----
    __half* Ch = Cho + cofs;
    const __half* R = HR ? resid + cofs : nullptr;

    float rs1[2][2] = {{0.f,0.f},{0.f,0.f}};    // MODE1 exp-sums or STATS sums
    float rs2[2][2] = {{0.f,0.f},{0.f,0.f}};    // STATS sumsq

    #pragma unroll
    for (int mt = 0; mt < 2; mt++) {
        #pragma unroll
        for (int nt = 0; nt < 16; nt++) {
            const int r0 = row0 + 32*wr + 16*mt + (lane >> 2);
            const int cc = col0 + 128*wc + 8*nt + 2*(lane & 3);
            float2 bv = make_float2(0.f, 0.f);
            if (HB) bv = *(const float2*)&bias[cc];
            #pragma unroll
            for (int hh = 0; hh < 2; hh++) {
                const int r = r0 + hh * 8;
                float v0, v1;
                if (MODE == 1) {
                    v0 = __expf(acc[mt][nt][2*hh]     * scale);
                    v1 = __expf(acc[mt][nt][2*hh + 1] * scale);
                    rs1[mt][hh] += v0 + v1;
                } else if (MODE == 2) {
                    const float inv = 1.0f / RS[r];
                    v0 = acc[mt][nt][2*hh]     * inv;
                    v1 = acc[mt][nt][2*hh + 1] * inv;
                } else {
                    v0 = acc[mt][nt][2*hh]     * scale;
                    v1 = acc[mt][nt][2*hh + 1] * scale;
                    if (HB) { v0 += bv.x; v1 += bv.y; }
                    if (HR) {
                        float2 rv = __half22float2(*(const __half2*)&R[(size_t)r * ldc + cc]);
                        v0 += rv.x; v1 += rv.y;
                    }
                    if (ACT == 1) { v0 = gelu_exact(v0); v1 = gelu_exact(v1); }
                    if (STATS) {
                        rs1[mt][hh] += v0 + v1;
                        rs2[mt][hh] += v0*v0 + v1*v1;
                    }
                }
                *(__half2*)&Ch[(size_t)r * ldc + cc] =
                    __halves2half2(__float2half_rn(v0), __float2half_rn(v1));
            }
        }
    }

    if (MODE == 1) {
        #pragma unroll
        for (int mt = 0; mt < 2; mt++)
            #pragma unroll
            for (int hh = 0; hh < 2; hh++) {
                float s = rs1[mt][hh];
                s += __shfl_xor_sync(0xffffffffu, s, 1);
                s += __shfl_xor_sync(0xffffffffu, s, 2);
                if ((lane & 3) == 0) {
                    const int r = row0 + 32*wr + 16*mt + (lane >> 2) + hh * 8;
                    atomicAdd(&RS[r], s);
                }
            }
    }

    if (STATS) {
        // combine the two col-band warps (wc=0/1) via smem, write partial to st4
        float2* sred = (float2*)dsm;
        #pragma unroll
        for (int mt = 0; mt < 2; mt++)
            #pragma unroll
            for (int hh = 0; hh < 2; hh++) {
                float s1 = rs1[mt][hh], s2 = rs2[mt][hh];
                s1 += __shfl_xor_sync(0xffffffffu, s1, 1);
                s1 += __shfl_xor_sync(0xffffffffu, s1, 2);
                s2 += __shfl_xor_sync(0xffffffffu, s2, 1);
                s2 += __shfl_xor_sync(0xffffffffu, s2, 2);
                rs1[mt][hh] = s1; rs2[mt][hh] = s2;
            }
        __syncthreads();
        if (wc == 0 && (lane & 3) == 0) {
            #pragma unroll
            for (int mt = 0; mt < 2; mt++)
                #pragma unroll
                for (int hh = 0; hh < 2; hh++) {
                    int rl = 32*wr + 16*mt + (lane >> 2) + hh * 8;
                    sred[rl] = make_float2(rs1[mt][hh], rs2[mt][hh]);
                }
        }
        __syncthreads();
        if (wc == 1 && (lane & 3) == 0) {
            #pragma unroll
            for (int mt = 0; mt < 2; mt++)
                #pragma unroll
                for (int hh = 0; hh < 2; hh++) {
                    int rl = 32*wr + 16*mt + (lane >> 2) + hh * 8;
                    float2 t = sred[rl];
                    st4[(size_t)(row0 + rl) * 4 + blockIdx.x] =
                        make_float2(t.x + rs1[mt][hh], t.y + rs2[mt][hh]);
                }
        }
    }
}

// ---------------- converter: fp32 -> fp16 ----------------
__global__ __launch_bounds__(256) void conv_hf_kernel(const float4* __restrict__ src,
                                                      uint2* __restrict__ h, int n4)
{
    int i = blockIdx.x * 256 + threadIdx.x;
    if (i < n4) h[i] = conv4h(src[i]);
}

// ---------------- V transpose ----------------
__global__ __launch_bounds__(256) void transpose_v(const __half* __restrict__ qv,
                                                   __half* __restrict__ vt)
{
    __shared__ __half t[32][34];
    const int bh = blockIdx.z, b = bh / Hc, h = bh % Hc;
    const int q0 = blockIdx.x * 32, d0 = blockIdx.y * 32;
    const int tx = threadIdx.x & 31, ty = threadIdx.x >> 5;
    const size_t so = (size_t)b * Lc * D3c + 2 * Dc + h * HDc;
    #pragma unroll
    for (int i = ty; i < 32; i += 8)
        t[i][tx] = qv[so + (size_t)(q0 + i) * D3c + d0 + tx];
    __syncthreads();
    const size_t dofs = (size_t)bh * HDc * Lc;
    #pragma unroll
    for (int i = ty; i < 32; i += 8)
        vt[dofs + (size_t)(d0 + i) * Lc + q0 + tx] = t[tx][i];
}

// ---------------- final layernorm: fp16 in, fp32 out ----------------
__global__ __launch_bounds__(256)
void layernorm_kernel(const __half* __restrict__ x, const float* __restrict__ g,
                      const float* __restrict__ b, float* __restrict__ outF)
{
    const int row = blockIdx.x;
    const int t   = threadIdx.x;
    const float4 v = h4_to_f4(((const uint2*)(x + (size_t)row * Dc))[t]);

    float s1 = v.x + v.y + v.z + v.w;
    float s2 = v.x*v.x + v.y*v.y + v.z*v.z + v.w*v.w;

    __shared__ float sh1[8], sh2[8];
    #pragma unroll
    for (int o = 16; o > 0; o >>= 1) {
        s1 += __shfl_down_sync(0xffffffffu, s1, o);
        s2 += __shfl_down_sync(0xffffffffu, s2, o);
    }
    if ((t & 31) == 0) { sh1[t >> 5] = s1; sh2[t >> 5] = s2; }
    __syncthreads();
    if (t < 8) {
        s1 = sh1[t]; s2 = sh2[t];
        #pragma unroll
        for (int o = 4; o > 0; o >>= 1) {
            s1 += __shfl_down_sync(0xffu, s1, o);
            s2 += __shfl_down_sync(0xffu, s2, o);
        }
        if (t == 0) { sh1[0] = s1; sh2[0] = s2; }
    }
    __syncthreads();

    const float mean = sh1[0] * (1.0f / Dc);
    const float var  = sh2[0] * (1.0f / Dc) - mean * mean;
    const float rstd = rsqrtf(var + 1e-5f);

    const float4 gv = ((const float4*)g)[t];
    const float4 bv = ((const float4*)b)[t];
    float4 r;
    r.x = (v.x - mean) * rstd * gv.x + bv.x;
    r.y = (v.y - mean) * rstd * gv.y + bv.y;
    r.z = (v.z - mean) * rstd * gv.z + bv.z;
    r.w = (v.w - mean) * rstd * gv.w + bv.w;
    ((float4*)(outF + (size_t)row * Dc))[t] = r;
}

// ---------------- host side ----------------
static void conv_on(cudaStream_t s, const float* src, __half* h, size_t n) {
    int n4 = (int)(n / 4);
    conv_hf_kernel<<<(n4 + 255) / 256, 256, 0, s>>>((const float4*)src, (uint2*)h, n4);
}

extern "C" void kernel_launch(void* const* d_in, const int* in_sizes, int n_in,
                              void* d_out, int out_size)
{
    const float* x    = (const float*)d_in[0];
    const float* w3d  = (const float*)d_in[1];
    const float* b3d  = (const float*)d_in[2];
    const float* ln1g = (const float*)d_in[3];
    const float* ln1b = (const float*)d_in[4];
    const float* wqkv = (const float*)d_in[5];
    const float* bqkv = (const float*)d_in[6];
    const float* wprj = (const float*)d_in[7];
    const float* bprj = (const float*)d_in[8];
    const float* ln2g = (const float*)d_in[9];
    const float* ln2b = (const float*)d_in[10];
    const float* w1   = (const float*)d_in[11];
    const float* b1   = (const float*)d_in[12];
    const float* w2   = (const float*)d_in[13];
    const float* b2   = (const float*)d_in[14];
    const float* lnfg = (const float*)d_in[15];
    const float* lnfb = (const float*)d_in[16];
    float* out = (float*)d_out;

    __half *h,*xp,*w3,*wq,*wp,*w1p,*w2p,*qv,*vt,*pp,*op,*fp;
    float* sm;
    float2* st4;
    cudaGetSymbolAddress((void**)&h,   g_h);
    cudaGetSymbolAddress((void**)&xp,  g_x);
    cudaGetSymbolAddress((void**)&w3,  g_w3);
    cudaGetSymbolAddress((void**)&wq,  g_wq);
    cudaGetSymbolAddress((void**)&wp,  g_wp);
    cudaGetSymbolAddress((void**)&w1p, g_w1);
    cudaGetSymbolAddress((void**)&w2p, g_w2);
    cudaGetSymbolAddress((void**)&qv,  g_qv);
    cudaGetSymbolAddress((void**)&vt,  g_vt);
    cudaGetSymbolAddress((void**)&pp,  g_p);
    cudaGetSymbolAddress((void**)&sm,  g_sm);
    cudaGetSymbolAddress((void**)&st4, g_st4);
    cudaGetSymbolAddress((void**)&op,  g_o);
    cudaGetSymbolAddress((void**)&fp,  g_f);

    static cudaStream_t s2 = nullptr;
    static cudaEvent_t eFork = nullptr, eConv = nullptr, eQkv = nullptr, eVt = nullptr;
    static bool smem_set = false;
    if (!s2) {
        cudaStreamCreateWithFlags(&s2, cudaStreamNonBlocking);
        cudaEventCreateWithFlags(&eFork, cudaEventDisableTiming);
        cudaEventCreateWithFlags(&eConv, cudaEventDisableTiming);
        cudaEventCreateWithFlags(&eQkv,  cudaEventDisableTiming);
        cudaEventCreateWithFlags(&eVt,   cudaEventDisableTiming);
    }
    if (!smem_set) {
        cudaFuncSetAttribute(tc_ghf<true,false,0,0,true,false>,  cudaFuncAttributeMaxDynamicSharedMemorySize, SM1);
        cudaFuncSetAttribute(tc_ghf<true,false,0,0,false,true>,  cudaFuncAttributeMaxDynamicSharedMemorySize, SM1);
        cudaFuncSetAttribute(tc_ghf<false,false,0,1,false,false>,cudaFuncAttributeMaxDynamicSharedMemorySize, SM1);
        cudaFuncSetAttribute(tc_ghf<false,false,0,2,false,false>,cudaFuncAttributeMaxDynamicSharedMemorySize, SM1);
        cudaFuncSetAttribute(tc_ghf<true,true,0,0,true,false>,   cudaFuncAttributeMaxDynamicSharedMemorySize, SM1);
        cudaFuncSetAttribute(tc_ghf<true,false,1,0,false,true>,  cudaFuncAttributeMaxDynamicSharedMemorySize, SM1);
        smem_set = true;
    }

    const dim3 blk(256);
    const size_t WQ = (size_t)D3c*Dc, WP = (size_t)Dc*Dc, W1 = (size_t)FFc*Dc, W2 = (size_t)Dc*FFc;

    // ---- fork: weight conversions on s2, overlapped with embed ----
    cudaEventRecord(eFork, 0);
    cudaStreamWaitEvent(s2, eFork, 0);
    for (int i = 0; i < NLc; i++) {
        conv_on(s2, wqkv + (size_t)i*WQ, wq  + (size_t)i*WQ, WQ);
        conv_on(s2, wprj + (size_t)i*WP, wp  + (size_t)i*WP, WP);
        conv_on(s2, w1   + (size_t)i*W1, w1p + (size_t)i*W1, W1);
        conv_on(s2, w2   + (size_t)i*W2, w2p + (size_t)i*W2, W2);
    }
    cudaEventRecord(eConv, s2);

    // ---- main stream ----
    conv_on(0, x,   xp, (size_t)Mc * D3c);
    conv_on(0, w3d, w3, (size_t)Dc * D3c);

    // embed: h = x @ w3d^T + b3d, with LN stats
    tc_ghf<true,false,0,0,true,false><<<dim3(Dc/256, Mc/128, 1), blk, SM1>>>(
        xp, D3c, w3, D3c, b3d, nullptr, nullptr, 0, 0, st4, nullptr, nullptr,
        h, Dc, D3c, 1.0f, 0,0,0,0,0,0, 1);

    cudaStreamWaitEvent(0, eConv, 0);

    for (int i = 0; i < NLc; i++) {
        const __half* wqi = wq  + (size_t)i*WQ;
        const __half* wpi = wp  + (size_t)i*WP;
        const __half* w1i = w1p + (size_t)i*W1;
        const __half* w2i = w2p + (size_t)i*W2;

        // qkv = LN1(h) @ wqkv^T + bqkv  (LN applied in loader)
        tc_ghf<true,false,0,0,false,true><<<dim3(D3c/256, Mc/128, 1), blk, SM1>>>(
            h, Dc, wqi, Dc, bqkv + (size_t)i*D3c, nullptr, nullptr, 0, 0,
            st4, ln1g + (size_t)i*Dc, ln1b + (size_t)i*Dc,
            qv, D3c, Dc, 1.0f, 0,0,0,0,0,0, 1);

        // transpose V on s2; zero row sums on main stream
        cudaEventRecord(eQkv, 0);
        cudaStreamWaitEvent(s2, eQkv, 0);
        transpose_v<<<dim3(Lc/32, HDc/32, Bc*Hc), blk, 0, s2>>>(qv, vt);
        cudaEventRecord(eVt, s2);

        cudaMemsetAsync(sm, 0, (size_t)Bc*Hc*Lc*sizeof(float), 0);

        // P = exp(scale * Q @ K^T); row sums via atomics
        tc_ghf<false,false,0,1,false,false><<<dim3(Lc/256, Lc/128, Bc*Hc), blk, SM1>>>(
            qv, D3c,
            qv + Dc, D3c,
            nullptr, nullptr,
            sm, (long)Hc*Lc, (long)Lc, nullptr, nullptr, nullptr,
            pp, Lc, HDc, 0.0625f,
            (long)Lc*D3c, (long)HDc,
            (long)Lc*D3c, (long)HDc,
            (long)Hc*Lc*Lc, (long)Lc*Lc,
            Hc);

        cudaStreamWaitEvent(0, eVt, 0);

        // o = (P @ Vt^T) / rowsum
        tc_ghf<false,false,0,2,false,false><<<dim3(HDc/256, Lc/128, Bc*Hc), blk, SM1>>>(
            pp, Lc,
            vt, Lc,
            nullptr, nullptr,
            sm, (long)Hc*Lc, (long)Lc, nullptr, nullptr, nullptr,
            op, Dc, Lc, 1.0f,
            (long)Hc*Lc*Lc, (long)Lc*Lc,
            (long)Hc*HDc*Lc, (long)HDc*Lc,
            (long)Lc*Dc, (long)HDc,
            Hc);

        // h = h + o @ wproj^T + bproj, with LN stats
        tc_ghf<true,true,0,0,true,false><<<dim3(Dc/256, Mc/128, 1), blk, SM1>>>(
            op, Dc, wpi, Dc, bprj + (size_t)i*Dc, h, nullptr, 0, 0,
            st4, nullptr, nullptr,
            h, Dc, Dc, 1.0f, 0,0,0,0,0,0, 1);

        // f = gelu(LN2(h) @ w1^T + b1)  (LN in loader)
        tc_ghf<true,false,1,0,false,true><<<dim3(FFc/256, Mc/128, 1), blk, SM1>>>(
            h, Dc, w1i, Dc, b1 + (size_t)i*FFc, nullptr, nullptr, 0, 0,
            st4, ln2g + (size_t)i*Dc, ln2b + (size_t)i*Dc,
            fp, FFc, Dc, 1.0f, 0,0,0,0,0,0, 1);

        // h = h + f @ w2^T + b2, with LN stats
        tc_ghf<true,true,0,0,true,false><<<dim3(Dc/256, Mc/128, 1), blk, SM1>>>(
            fp, FFc, w2i, FFc, b2 + (size_t)i*Dc, h, nullptr, 0, 0,
            st4, nullptr, nullptr,
            h, Dc, FFc, 1.0f, 0,0,0,0,0,0, 1);
    }

    layernorm_kernel<<<Mc, blk>>>(h, lnfg, lnfb, out);
}

// round 17
// speedup vs baseline: 1.0362x; 1.0362x over previous
#include <cuda_runtime.h>
#include <cuda_fp16.h>
#include <math.h>
#include <stdint.h>

// ---------------- problem constants ----------------
#define Bc   4
#define Lc   2048
#define Dc   1024
#define Hc   4
#define HDc  256
#define NLc  2
#define FFc  4096
#define Mc   (Bc*Lc)     // 8192 tokens
#define D3c  (3*Dc)      // 3072

// ---------------- device scratch (static; no allocations) ----------------
__device__ __align__(16) __half g_h  [(size_t)Mc*Dc];        // residual fp16
__device__ __align__(16) __half g_x  [(size_t)Mc*D3c];
__device__ __align__(16) __half g_w3 [(size_t)Dc*D3c];
__device__ __align__(16) __half g_hn [(size_t)Mc*Dc];
__device__ __align__(16) __half g_wq [(size_t)NLc*D3c*Dc];
__device__ __align__(16) __half g_wp [(size_t)NLc*Dc*Dc];
__device__ __align__(16) __half g_w1 [(size_t)NLc*FFc*Dc];
__device__ __align__(16) __half g_w2 [(size_t)NLc*Dc*FFc];
__device__ __align__(16) __half g_qv [(size_t)Mc*D3c];
__device__ __align__(16) __half g_vt [(size_t)Bc*Hc*HDc*Lc];
__device__ __align__(16) __half g_p  [(size_t)Bc*Hc*Lc*Lc]; // exp(logits), unnormalized
__device__ __align__(8)  float  g_sm [(size_t)NLc*Bc*Hc*Lc];// per-row exp sums, per layer
__device__ __align__(16) __half g_o  [(size_t)Mc*Dc];
__device__ __align__(16) __half g_f  [(size_t)Mc*FFc];

// ---------------- helpers ----------------
__device__ __forceinline__ uint32_t smem_u32(const void* p) {
    uint32_t a;
    asm("{ .reg .u64 t; cvta.to.shared.u64 t, %1; cvt.u32.u64 %0, t; }" : "=r"(a) : "l"(p));
    return a;
}
__device__ __forceinline__ void ldsm4(uint32_t* r, uint32_t addr) {
    asm volatile("ldmatrix.sync.aligned.m8n8.x4.shared.b16 {%0,%1,%2,%3}, [%4];"
        : "=r"(r[0]), "=r"(r[1]), "=r"(r[2]), "=r"(r[3]) : "r"(addr));
}
__device__ __forceinline__ void mma_hf(float* d, const uint32_t* a, const uint32_t* b) {
    asm volatile(
        "mma.sync.aligned.m16n8k16.row.col.f32.f16.f16.f32 "
        "{%0,%1,%2,%3}, {%4,%5,%6,%7}, {%8,%9}, {%0,%1,%2,%3};"
        : "+f"(d[0]), "+f"(d[1]), "+f"(d[2]), "+f"(d[3])
        : "r"(a[0]), "r"(a[1]), "r"(a[2]), "r"(a[3]), "r"(b[0]), "r"(b[1]));
}
__device__ __forceinline__ void cpa16(uint32_t dst, const void* src) {
    asm volatile("cp.async.cg.shared.global [%0], [%1], 16;" :: "r"(dst), "l"(src));
}
#define CP_COMMIT() asm volatile("cp.async.commit_group;" ::: "memory")
#define CP_WAIT1()  asm volatile("cp.async.wait_group 1;"  ::: "memory")

__device__ __forceinline__ float gelu_exact(float x) {
    return 0.5f * x * (1.0f + erff(x * 0.70710678118654752440f));
}
__device__ __forceinline__ uint2 conv4h(float4 v) {
    union { __half2 h2[2]; uint2 u; } H;
    H.h2[0] = __halves2half2(__float2half_rn(v.x), __float2half_rn(v.y));
    H.h2[1] = __halves2half2(__float2half_rn(v.z), __float2half_rn(v.w));
    return H.u;
}
__device__ __forceinline__ float4 h4_to_f4(uint2 u) {
    union { uint2 uu; __half2 h2[2]; } U; U.uu = u;
    float2 lo = __half22float2(U.h2[0]);
    float2 hi = __half22float2(U.h2[1]);
    return make_float4(lo.x, lo.y, hi.x, hi.y);
}

// ================= fp16 1-term GEMM, CTA tile 128x256, fp16 out =================
// MODE 0: C = act(scale*A@B^T + bias + resid)
// MODE 1: C = exp(scale*A@B^T), atomicAdd per-row sums into rowsum
// MODE 2: C = (A@B^T) * (1/rowsum[row])
#define KC     64
#define SKB    72
#define A_TILE (128*SKB*2)          // 18432 B
#define B_TILE (256*SKB*2)          // 36864 B
#define STG    (A_TILE + B_TILE)    // 55296 B
#define SM1    (3*STG)              // 165888 B dynamic smem

template<bool HB, bool HR, int ACT, int MODE>
__global__ __launch_bounds__(256, 1) void tc_ghf(
    const __half* __restrict__ Ah, int lda,
    const __half* __restrict__ Bh, int ldb,
    const float* __restrict__ bias,
    const __half* __restrict__ resid,
    float* __restrict__ rowsum, long sto, long sti,
    __half* __restrict__ Cho, int ldc,
    int K, float scale,
    long aso, long asi, long bso, long bsi, long cso, long csi, int zinner)
{
    const int z  = blockIdx.z;
    const int zo = z / zinner;
    const int zi = z - zo * zinner;
    const size_t aofs = (size_t)zo * aso + (size_t)zi * asi;
    const size_t bofs = (size_t)zo * bso + (size_t)zi * bsi;
    const size_t cofs = (size_t)zo * cso + (size_t)zi * csi;
    Ah += aofs;
    Bh += bofs;

    extern __shared__ char dsm[];
    const uint32_t sb32 = smem_u32(dsm);

    const int tid  = threadIdx.x;
    const int wid  = tid >> 5;
    const int lane = tid & 31;
    const int wr   = wid & 3;
    const int wc   = wid >> 2;
    const int row0 = blockIdx.y * 128;
    const int col0 = blockIdx.x * 256;

    const int lr0 = tid >> 3;
    const int lc8 = (tid & 7) << 3;

    const __half* A0 = Ah + (size_t)row0 * lda;
    const __half* B0 = Bh + (size_t)col0 * ldb;

    float* RS = (MODE != 0) ? rowsum + (size_t)zo * sto + (size_t)zi * sti : nullptr;

    float acc[2][16][4];
    #pragma unroll
    for (int mt = 0; mt < 2; mt++)
        #pragma unroll
        for (int nt = 0; nt < 16; nt++)
            #pragma unroll
            for (int j = 0; j < 4; j++) acc[mt][nt][j] = 0.0f;

    const int nc = K / KC;

    auto load_stage = [&](int stg, int k0) {
        uint32_t base = sb32 + (uint32_t)stg * STG;
        #pragma unroll
        for (int it = 0; it < 4; it++) {
            int r = lr0 + it * 32;
            cpa16(base + (uint32_t)(r * SKB + lc8) * 2, A0 + (size_t)r * lda + k0 + lc8);
        }
        #pragma unroll
        for (int it = 0; it < 8; it++) {
            int r = lr0 + it * 32;
            cpa16(base + A_TILE + (uint32_t)(r * SKB + lc8) * 2, B0 + (size_t)r * ldb + k0 + lc8);
        }
    };

    load_stage(0, 0);
    CP_COMMIT();
    if (nc > 1) load_stage(1, KC);
    CP_COMMIT();

    const int ro = lane & 15;
    const int co = (lane >> 4) << 3;

    for (int c = 0; c < nc; c++) {
        CP_WAIT1();
        __syncthreads();

        if (c + 2 < nc) load_stage((c + 2) % 3, (c + 2) * KC);
        CP_COMMIT();

        const uint32_t sOff = sb32 + (uint32_t)(c % 3) * STG;
        #pragma unroll
        for (int ks = 0; ks < 4; ks++) {
            const int k0 = ks * 16;
            uint32_t ah[2][4];
            #pragma unroll
            for (int mt = 0; mt < 2; mt++) {
                uint32_t off = (uint32_t)((32*wr + 16*mt + ro) * SKB + k0 + co) * 2;
                ldsm4(ah[mt], sOff + off);
            }
            uint32_t bh[16][2];
            #pragma unroll
            for (int p = 0; p < 8; p++) {
                uint32_t off = (uint32_t)((128*wc + 16*p + ro) * SKB + k0 + co) * 2;
                uint32_t r[4];
                ldsm4(r, sOff + A_TILE + off);
                bh[2*p][0] = r[0];   bh[2*p][1] = r[2];
                bh[2*p+1][0] = r[1]; bh[2*p+1][1] = r[3];
            }
            #pragma unroll
            for (int mt = 0; mt < 2; mt++)
                #pragma unroll
                for (int nt = 0; nt < 16; nt++)
                    mma_hf(acc[mt][nt], ah[mt], bh[nt]);
        }
        __syncthreads();
    }

    // ---- epilogue ----
    __half* Ch = Cho + cofs;
    const __half* R = HR ? resid + cofs : nullptr;

    float rs[2][2] = {{0.f, 0.f}, {0.f, 0.f}};   // MODE 1 row partial sums

    #pragma unroll
    for (int mt = 0; mt < 2; mt++) {
        #pragma unroll
        for (int nt = 0; nt < 16; nt++) {
            const int r0 = row0 + 32*wr + 16*mt + (lane >> 2);
            const int cc = col0 + 128*wc + 8*nt + 2*(lane & 3);
            float2 bv = make_float2(0.f, 0.f);
            if (HB) bv = *(const float2*)&bias[cc];
            #pragma unroll
            for (int hh = 0; hh < 2; hh++) {
                const int r = r0 + hh * 8;
                float v0, v1;
                if (MODE == 1) {
                    v0 = __expf(acc[mt][nt][2*hh]     * scale);
                    v1 = __expf(acc[mt][nt][2*hh + 1] * scale);
                    rs[mt][hh] += v0 + v1;
                } else if (MODE == 2) {
                    const float inv = 1.0f / RS[r];
                    v0 = acc[mt][nt][2*hh]     * inv;
                    v1 = acc[mt][nt][2*hh + 1] * inv;
                } else {
                    v0 = acc[mt][nt][2*hh]     * scale;
                    v1 = acc[mt][nt][2*hh + 1] * scale;
                    if (HB) { v0 += bv.x; v1 += bv.y; }
                    if (HR) {
                        float2 rv = __half22float2(*(const __half2*)&R[(size_t)r * ldc + cc]);
                        v0 += rv.x; v1 += rv.y;
                    }
                    if (ACT == 1) { v0 = gelu_exact(v0); v1 = gelu_exact(v1); }
                }
                *(__half2*)&Ch[(size_t)r * ldc + cc] =
                    __halves2half2(__float2half_rn(v0), __float2half_rn(v1));
            }
        }
    }

    if (MODE == 1) {
        #pragma unroll
        for (int mt = 0; mt < 2; mt++)
            #pragma unroll
            for (int hh = 0; hh < 2; hh++) {
                float s = rs[mt][hh];
                s += __shfl_xor_sync(0xffffffffu, s, 1);
                s += __shfl_xor_sync(0xffffffffu, s, 2);
                if ((lane & 3) == 0) {
                    const int r = row0 + 32*wr + 16*mt + (lane >> 2) + hh * 8;
                    atomicAdd(&RS[r], s);
                }
            }
    }
}

// ---------------- converter: fp32 -> fp16 ----------------
__global__ __launch_bounds__(256) void conv_hf_kernel(const float4* __restrict__ src,
                                                      uint2* __restrict__ h, int n4)
{
    int i = blockIdx.x * 256 + threadIdx.x;
    if (i < n4) h[i] = conv4h(src[i]);
}

// ---------------- V transpose ----------------
__global__ __launch_bounds__(256) void transpose_v(const __half* __restrict__ qv,
                                                   __half* __restrict__ vt)
{
    __shared__ __half t[32][34];
    const int bh = blockIdx.z, b = bh / Hc, h = bh % Hc;
    const int q0 = blockIdx.x * 32, d0 = blockIdx.y * 32;
    const int tx = threadIdx.x & 31, ty = threadIdx.x >> 5;
    const size_t so = (size_t)b * Lc * D3c + 2 * Dc + h * HDc;
    #pragma unroll
    for (int i = ty; i < 32; i += 8)
        t[i][tx] = qv[so + (size_t)(q0 + i) * D3c + d0 + tx];
    __syncthreads();
    const size_t dofs = (size_t)bh * HDc * Lc;
    #pragma unroll
    for (int i = ty; i < 32; i += 8)
        vt[dofs + (size_t)(d0 + i) * Lc + q0 + tx] = t[tx][i];
}

// ---------------- layernorm ----------------
template<int OMODE>
__global__ __launch_bounds__(256)
void layernorm_kernel(const __half* __restrict__ x, const float* __restrict__ g,
                      const float* __restrict__ b,
                      float* __restrict__ outF, __half* __restrict__ outH)
{
    const int row = blockIdx.x;
    const int t   = threadIdx.x;
    const float4 v = h4_to_f4(((const uint2*)(x + (size_t)row * Dc))[t]);

    float s1 = v.x + v.y + v.z + v.w;
    float s2 = v.x*v.x + v.y*v.y + v.z*v.z + v.w*v.w;

    __shared__ float sh1[8], sh2[8];
    #pragma unroll
    for (int o = 16; o > 0; o >>= 1) {
        s1 += __shfl_down_sync(0xffffffffu, s1, o);
        s2 += __shfl_down_sync(0xffffffffu, s2, o);
    }
    if ((t & 31) == 0) { sh1[t >> 5] = s1; sh2[t >> 5] = s2; }
    __syncthreads();
    if (t < 8) {
        s1 = sh1[t]; s2 = sh2[t];
        #pragma unroll
        for (int o = 4; o > 0; o >>= 1) {
            s1 += __shfl_down_sync(0xffu, s1, o);
            s2 += __shfl_down_sync(0xffu, s2, o);
        }
        if (t == 0) { sh1[0] = s1; sh2[0] = s2; }
    }
    __syncthreads();

    const float mean = sh1[0] * (1.0f / Dc);
    const float var  = sh2[0] * (1.0f / Dc) - mean * mean;
    const float rstd = rsqrtf(var + 1e-5f);

    const float4 gv = ((const float4*)g)[t];
    const float4 bv = ((const float4*)b)[t];
    float4 r;
    r.x = (v.x - mean) * rstd * gv.x + bv.x;
    r.y = (v.y - mean) * rstd * gv.y + bv.y;
    r.z = (v.z - mean) * rstd * gv.z + bv.z;
    r.w = (v.w - mean) * rstd * gv.w + bv.w;
    if (OMODE == 1) {
        ((uint2*)(outH + (size_t)row * Dc))[t] = conv4h(r);
    } else {
        ((float4*)(outF + (size_t)row * Dc))[t] = r;
    }
}

// ---------------- host side ----------------
static void conv_on(cudaStream_t s, const float* src, __half* h, size_t n) {
    int n4 = (int)(n / 4);
    conv_hf_kernel<<<(n4 + 255) / 256, 256, 0, s>>>((const float4*)src, (uint2*)h, n4);
}

extern "C" void kernel_launch(void* const* d_in, const int* in_sizes, int n_in,
                              void* d_out, int out_size)
{
    const float* x    = (const float*)d_in[0];
    const float* w3d  = (const float*)d_in[1];
    const float* b3d  = (const float*)d_in[2];
    const float* ln1g = (const float*)d_in[3];
    const float* ln1b = (const float*)d_in[4];
    const float* wqkv = (const float*)d_in[5];
    const float* bqkv = (const float*)d_in[6];
    const float* wprj = (const float*)d_in[7];
    const float* bprj = (const float*)d_in[8];
    const float* ln2g = (const float*)d_in[9];
    const float* ln2b = (const float*)d_in[10];
    const float* w1   = (const float*)d_in[11];
    const float* b1   = (const float*)d_in[12];
    const float* w2   = (const float*)d_in[13];
    const float* b2   = (const float*)d_in[14];
    const float* lnfg = (const float*)d_in[15];
    const float* lnfb = (const float*)d_in[16];
    float* out = (float*)d_out;

    __half *h,*xp,*w3,*hn,*wq,*wp,*w1p,*w2p,*qv,*vt,*pp,*op,*fp;
    float* sm;
    cudaGetSymbolAddress((void**)&h,   g_h);
    cudaGetSymbolAddress((void**)&xp,  g_x);
    cudaGetSymbolAddress((void**)&w3,  g_w3);
    cudaGetSymbolAddress((void**)&hn,  g_hn);
    cudaGetSymbolAddress((void**)&wq,  g_wq);
    cudaGetSymbolAddress((void**)&wp,  g_wp);
    cudaGetSymbolAddress((void**)&w1p, g_w1);
    cudaGetSymbolAddress((void**)&w2p, g_w2);
    cudaGetSymbolAddress((void**)&qv,  g_qv);
    cudaGetSymbolAddress((void**)&vt,  g_vt);
    cudaGetSymbolAddress((void**)&pp,  g_p);
    cudaGetSymbolAddress((void**)&sm,  g_sm);
    cudaGetSymbolAddress((void**)&op,  g_o);
    cudaGetSymbolAddress((void**)&fp,  g_f);

    static cudaStream_t s2 = nullptr;
    static cudaEvent_t eFork = nullptr, eConv = nullptr, eW3 = nullptr, eQkv = nullptr, eVt = nullptr;
    static bool smem_set = false;
    if (!s2) {
        cudaStreamCreateWithFlags(&s2, cudaStreamNonBlocking);
        cudaEventCreateWithFlags(&eFork, cudaEventDisableTiming);
        cudaEventCreateWithFlags(&eConv, cudaEventDisableTiming);
        cudaEventCreateWithFlags(&eW3,   cudaEventDisableTiming);
        cudaEventCreateWithFlags(&eQkv,  cudaEventDisableTiming);
        cudaEventCreateWithFlags(&eVt,   cudaEventDisableTiming);
    }
    if (!smem_set) {
        cudaFuncSetAttribute(tc_ghf<true,false,0,0>,  cudaFuncAttributeMaxDynamicSharedMemorySize, SM1);
        cudaFuncSetAttribute(tc_ghf<false,false,0,1>, cudaFuncAttributeMaxDynamicSharedMemorySize, SM1);
        cudaFuncSetAttribute(tc_ghf<false,false,0,2>, cudaFuncAttributeMaxDynamicSharedMemorySize, SM1);
        cudaFuncSetAttribute(tc_ghf<true,true,0,0>,   cudaFuncAttributeMaxDynamicSharedMemorySize, SM1);
        cudaFuncSetAttribute(tc_ghf<true,false,1,0>,  cudaFuncAttributeMaxDynamicSharedMemorySize, SM1);
        smem_set = true;
    }

    const dim3 blk(256);
    const size_t WQ = (size_t)D3c*Dc, WP = (size_t)Dc*Dc, W1 = (size_t)FFc*Dc, W2 = (size_t)Dc*FFc;
    const size_t SMN = (size_t)Bc*Hc*Lc;

    // ---- fork: w3 conv, weight convs, rowsum memsets all on s2 ----
    cudaEventRecord(eFork, 0);
    cudaStreamWaitEvent(s2, eFork, 0);
    conv_on(s2, w3d, w3, (size_t)Dc * D3c);
    cudaEventRecord(eW3, s2);
    for (int i = 0; i < NLc; i++) {
        conv_on(s2, wqkv + (size_t)i*WQ, wq  + (size_t)i*WQ, WQ);
        conv_on(s2, wprj + (size_t)i*WP, wp  + (size_t)i*WP, WP);
        conv_on(s2, w1   + (size_t)i*W1, w1p + (size_t)i*W1, W1);
        conv_on(s2, w2   + (size_t)i*W2, w2p + (size_t)i*W2, W2);
    }
    cudaMemsetAsync(sm, 0, NLc * SMN * sizeof(float), s2);
    cudaEventRecord(eConv, s2);

    // ---- main stream: x conversion (concurrent with w3 on s2) ----
    conv_on(0, x, xp, (size_t)Mc * D3c);
    cudaStreamWaitEvent(0, eW3, 0);

    // embed: h = x @ w3d^T + b3d
    tc_ghf<true,false,0,0><<<dim3(Dc/256, Mc/128, 1), blk, SM1>>>(
        xp, D3c, w3, D3c, b3d, nullptr, nullptr, 0, 0,
        h, Dc, D3c, 1.0f, 0,0,0,0,0,0, 1);

    cudaStreamWaitEvent(0, eConv, 0);   // weights + memsets ready

    for (int i = 0; i < NLc; i++) {
        const __half* wqi = wq  + (size_t)i*WQ;
        const __half* wpi = wp  + (size_t)i*WP;
        const __half* w1i = w1p + (size_t)i*W1;
        const __half* w2i = w2p + (size_t)i*W2;
        float* smi = sm + (size_t)i * SMN;

        layernorm_kernel<1><<<Mc, blk>>>(h, ln1g + (size_t)i*Dc, ln1b + (size_t)i*Dc,
                                         nullptr, hn);

        tc_ghf<true,false,0,0><<<dim3(D3c/256, Mc/128, 1), blk, SM1>>>(
            hn, Dc, wqi, Dc, bqkv + (size_t)i*D3c, nullptr, nullptr, 0, 0,
            qv, D3c, Dc, 1.0f, 0,0,0,0,0,0, 1);

        // transpose V on s2, overlapped with QK
        cudaEventRecord(eQkv, 0);
        cudaStreamWaitEvent(s2, eQkv, 0);
        transpose_v<<<dim3(Lc/32, HDc/32, Bc*Hc), blk, 0, s2>>>(qv, vt);
        cudaEventRecord(eVt, s2);

        // P = exp(scale * Q @ K^T); row sums via atomics
        tc_ghf<false,false,0,1><<<dim3(Lc/256, Lc/128, Bc*Hc), blk, SM1>>>(
            qv, D3c,
            qv + Dc, D3c,
            nullptr, nullptr,
            smi, (long)Hc*Lc, (long)Lc,
            pp, Lc, HDc, 0.0625f,
            (long)Lc*D3c, (long)HDc,
            (long)Lc*D3c, (long)HDc,
            (long)Hc*Lc*Lc, (long)Lc*Lc,
            Hc);

        cudaStreamWaitEvent(0, eVt, 0);

        // o = (P @ Vt^T) / rowsum
        tc_ghf<false,false,0,2><<<dim3(HDc/256, Lc/128, Bc*Hc), blk, SM1>>>(
            pp, Lc,
            vt, Lc,
            nullptr, nullptr,
            smi, (long)Hc*Lc, (long)Lc,
            op, Dc, Lc, 1.0f,
            (long)Hc*Lc*Lc, (long)Lc*Lc,
            (long)Hc*HDc*Lc, (long)HDc*Lc,
            (long)Lc*Dc, (long)HDc,
            Hc);

        tc_ghf<true,true,0,0><<<dim3(Dc/256, Mc/128, 1), blk, SM1>>>(
            op, Dc, wpi, Dc, bprj + (size_t)i*Dc, h, nullptr, 0, 0,
            h, Dc, Dc, 1.0f, 0,0,0,0,0,0, 1);

        layernorm_kernel<1><<<Mc, blk>>>(h, ln2g + (size_t)i*Dc, ln2b + (size_t)i*Dc,
                                         nullptr, hn);

        tc_ghf<true,false,1,0><<<dim3(FFc/256, Mc/128, 1), blk, SM1>>>(
            hn, Dc, w1i, Dc, b1 + (size_t)i*FFc, nullptr, nullptr, 0, 0,
            fp, FFc, Dc, 1.0f, 0,0,0,0,0,0, 1);

        tc_ghf<true,true,0,0><<<dim3(Dc/256, Mc/128, 1), blk, SM1>>>(
            fp, FFc, w2i, FFc, b2 + (size_t)i*Dc, h, nullptr, 0, 0,
            h, Dc, FFc, 1.0f, 0,0,0,0,0,0, 1);
    }

    layernorm_kernel<0><<<Mc, blk>>>(h, lnfg, lnfb, out, nullptr);
}